// round 5
// baseline (speedup 1.0000x reference)
#include <cuda_runtime.h>
#include <cstdint>

// GlobalFilter: y = irfft(rfft(x, n=10) * W, n=10) == per-dim length-10 circular conv.
// x: [B=8192, DIM=1024, N=10] f32, W: [DIM, 6, 2] f32, y: [B, DIM, 10] f32.
// Single fused kernel: filter taps h computed per-thread from W, hidden under cp.async.

#define DIM            1024
#define NPTS           10
#define THREADS        256
#define ROWS_PER_BLOCK 512                           // 2 rows per thread
#define F4_PER_BLOCK   (ROWS_PER_BLOCK * NPTS / 4)   // 1280 float4 per block
#define F4_PER_WARP    160
#define XBUF_BYTES     (THREADS * 80)                // 20480 (2560 per warp)
#define WSTRIDE        112                           // padded per-thread w region (16B-aligned,
                                                     // word 28t mod 32 -> conflict-free LDS.128)
#define WBUF_PW        (32 * WSTRIDE)                // 3584 per warp
#define SMEM_TOTAL     (XBUF_BYTES + 8 * WBUF_PW)    // 20480 + 28672 = 49152 (48KB exactly)

// ---- packed f32x2 helpers ----
__device__ __forceinline__ unsigned long long pack2(float lo, float hi) {
    unsigned long long r;
    asm("mov.b64 %0, {%1, %2};" : "=l"(r) : "f"(lo), "f"(hi));
    return r;
}
__device__ __forceinline__ unsigned long long fma2(unsigned long long a,
                                                   unsigned long long b,
                                                   unsigned long long c) {
    unsigned long long d;
    asm("fma.rn.f32x2 %0, %1, %2, %3;" : "=l"(d) : "l"(a), "l"(b), "l"(c));
    return d;
}
__device__ __forceinline__ void unpack2(unsigned long long v, float& lo, float& hi) {
    asm("mov.b64 {%0, %1}, %2;" : "=f"(lo), "=f"(hi) : "l"(v));
}
__device__ __forceinline__ uint32_t smem_u32(const void* p) {
    return (uint32_t)__cvta_generic_to_shared(p);
}

// h_d[j] = 0.1*( a0 + (-1)^j a5 + 2*sum_{k=1..4} ( a_k cos(2πkj/10) - b_k sin(2πkj/10) ) )
// Split k into even {2,4} (E_j, invariant under j->j+5) and odd {1,3} (O_j, sign-flips):
//   h[j]   = q_j  + E_j + O_j
//   h[j+5] = q'_j + E_j - O_j,   q_j = 0.1(a0 + σ_j a5),  q'_j = q_j - 0.2 σ_j a5, σ_j=(-1)^j
__device__ __forceinline__ void compute_h(const float* __restrict__ wd, float h[10]) {
    // Folded constants: CC[m] = 0.2*cos(2πm/10), SS[m] = -0.2*sin(2πm/10)
    constexpr float CC[10] = {
        0.2f,  0.16180339887498949f,  0.061803398874989485f, -0.061803398874989485f, -0.16180339887498949f,
       -0.2f, -0.16180339887498949f, -0.061803398874989485f,  0.061803398874989485f,  0.16180339887498949f};
    constexpr float SS[10] = {
        0.0f, -0.11755705045849463f, -0.19021130325903071f, -0.19021130325903071f, -0.11755705045849463f,
        0.0f,  0.11755705045849463f,  0.19021130325903071f,  0.19021130325903071f,  0.11755705045849463f};

    float a0 = wd[0], a1 = wd[2], b1 = wd[3], a2 = wd[4], b2 = wd[5];
    float a3 = wd[6], b3 = wd[7], a4 = wd[8], b4 = wd[9], a5 = wd[10];

    float t0 = 0.1f * a0;
    float qe = fmaf(a5, 0.1f, t0);    // j even
    float qo = fmaf(a5, -0.1f, t0);   // j odd

#pragma unroll
    for (int j = 0; j < 5; j++) {
        float q = (j & 1) ? qo : qe;
        float e = q;
        e = fmaf(a2, CC[(2 * j) % 10], e);
        e = fmaf(b2, SS[(2 * j) % 10], e);
        e = fmaf(a4, CC[(4 * j) % 10], e);
        e = fmaf(b4, SS[(4 * j) % 10], e);
        float o = a1 * CC[j];
        o = fmaf(b1, SS[j], o);
        o = fmaf(a3, CC[(3 * j) % 10], o);
        o = fmaf(b3, SS[(3 * j) % 10], o);
        h[j] = e + o;
        float e2 = fmaf(a5, (j & 1) ? 0.2f : -0.2f, e);   // q' + E
        h[j + 5] = e2 - o;
    }
}

__global__ void __launch_bounds__(THREADS, 4)
global_filter_kernel(const float* __restrict__ x, const float* __restrict__ wg,
                     float* __restrict__ y) {
    __shared__ __align__(16) char smem[SMEM_TOTAL];

    int tid = threadIdx.x;
    int w   = tid >> 5;      // warp in block
    int t   = tid & 31;      // lane

    char* xw = smem + w * 2560;                    // warp's x staging tile
    char* ww = smem + XBUF_BYTES + w * WBUF_PW;    // warp's w exchange buffer

    size_t f4base = (size_t)blockIdx.x * F4_PER_BLOCK + (size_t)w * F4_PER_WARP;
    const float4* xg = reinterpret_cast<const float4*>(x) + f4base;

    // Phase 1: x global -> smem via cp.async (L1 bypass, no registers)
#pragma unroll
    for (int k = 0; k < 5; k++) {
        uint32_t sa = smem_u32(xw + (t + 32 * k) * 16);
        const float4* ga = xg + t + 32 * k;
        asm volatile("cp.async.cg.shared.global [%0], [%1], 16;\n" :: "r"(sa), "l"(ga));
    }
    asm volatile("cp.async.commit_group;\n");

    // Phase 2 (overlapped with x latency): coalesced w load -> padded smem exchange.
    // Block covers 512 rows = 256 pairs; warp w covers pairs [pwb, pwb+32).
    int pwb = (blockIdx.x * THREADS + w * 32) & (DIM / 2 - 1);
    const float4* wf4 = reinterpret_cast<const float4*>(wg) + (size_t)pwb * 6;
#pragma unroll
    for (int k = 0; k < 6; k++) {
        int idx = t + 32 * k;             // 0..191
        float4 v = wf4[idx];
        int d = idx / 6, m = idx % 6;
        *reinterpret_cast<float4*>(ww + d * WSTRIDE + m * 16) = v;
    }
    __syncwarp();

    // Each thread reads its own pair's 24 floats (dims 2p, 2p+1), conflict-free LDS.128.
    float wv[24];
    {
        const float4* sp = reinterpret_cast<const float4*>(ww + t * WSTRIDE);
#pragma unroll
        for (int i = 0; i < 6; i++) {
            float4 v = sp[i];
            wv[4 * i] = v.x; wv[4 * i + 1] = v.y; wv[4 * i + 2] = v.z; wv[4 * i + 3] = v.w;
        }
    }

    // Compute filter taps for both dims, pack as (h_even_dim, h_odd_dim).
    float h0[10], h1[10];
    compute_h(wv, h0);
    compute_h(wv + 12, h1);
    unsigned long long hv[10];
#pragma unroll
    for (int j = 0; j < 10; j++) hv[j] = pack2(h0[j], h1[j]);

    asm volatile("cp.async.wait_group 0;\n");
    __syncwarp();

    // Phase 3: thread reads its OWN 80B (rows 2t, 2t+1), conflict-free LDS.128.
    const float4* sx = reinterpret_cast<const float4*>(xw + 80 * t);
    float4 r0 = sx[0], r1 = sx[1], r2 = sx[2], r3 = sx[3], r4 = sx[4];
    float xr[20] = {r0.x, r0.y, r0.z, r0.w, r1.x, r1.y, r1.z, r1.w, r2.x, r2.y,
                    r2.z, r2.w, r3.x, r3.y, r3.z, r3.w, r4.x, r4.y, r4.z, r4.w};

    unsigned long long xv[10];
#pragma unroll
    for (int j = 0; j < 10; j++) xv[j] = pack2(xr[j], xr[10 + j]);

    unsigned long long acc[10];
#pragma unroll
    for (int n = 0; n < 10; n++) acc[n] = 0ULL;
#pragma unroll
    for (int j = 0; j < 10; j++) {
#pragma unroll
        for (int n = 0; n < 10; n++) {
            acc[n] = fma2(hv[(n - j + 10) % 10], xv[j], acc[n]);
        }
    }

    // Phase 4: own-region STS, then warp-coalesced streaming stores.
    float y0[10], y1[10];
#pragma unroll
    for (int n = 0; n < 10; n++) unpack2(acc[n], y0[n], y1[n]);

    float4* sy = reinterpret_cast<float4*>(xw + 80 * t);
    sy[0] = make_float4(y0[0], y0[1], y0[2], y0[3]);
    sy[1] = make_float4(y0[4], y0[5], y0[6], y0[7]);
    sy[2] = make_float4(y0[8], y0[9], y1[0], y1[1]);
    sy[3] = make_float4(y1[2], y1[3], y1[4], y1[5]);
    sy[4] = make_float4(y1[6], y1[7], y1[8], y1[9]);
    __syncwarp();

    float4* yg = reinterpret_cast<float4*>(y) + f4base;
    const float4* sr = reinterpret_cast<const float4*>(xw);
#pragma unroll
    for (int k = 0; k < 5; k++) {
        __stcs(yg + t + 32 * k, sr[t + 32 * k]);
    }
}

extern "C" void kernel_launch(void* const* d_in, const int* in_sizes, int n_in,
                              void* d_out, int out_size) {
    const float* x = (const float*)d_in[0];
    const float* w = (const float*)d_in[1];
    float* y = (float*)d_out;

    int nrows  = in_sizes[0] / NPTS;            // 8192*1024 = 8,388,608
    int blocks = nrows / ROWS_PER_BLOCK;        // 16384
    global_filter_kernel<<<blocks, THREADS>>>(x, w, y);
}

// round 6
// speedup vs baseline: 1.0791x; 1.0791x over previous
#include <cuda_runtime.h>
#include <cstdint>

// GlobalFilter: y = irfft(rfft(x, n=10) * W, n=10) == per-dim length-10 circular conv.
// x: [B=8192, DIM=1024, N=10] f32, W: [DIM, 6, 2] f32, y: [B, DIM, 10] f32.
// Two kernels overlapped with programmatic dependent launch (PDL): the main kernel
// launches while precompute runs, issues its x cp.asyncs, then griddepcontrol.wait's
// before reading the filter table.

#define DIM            1024
#define NPTS           10
#define THREADS        256
#define ROWS_PER_BLOCK 512                       // 2 rows per thread
#define F4_PER_BLOCK   (ROWS_PER_BLOCK * NPTS / 4)   // 1280 float4 per block
#define F4_PER_WARP    160
#define SMEM_BYTES     (THREADS * 80)            // 20480 B (2560 B per warp)

// Transposed, pair-packed filter: g_hvT[j*512 + p] = (h[2p][j], h[2p+1][j]) as 2 floats.
__device__ unsigned long long g_hvT[NPTS * (DIM / 2)];

__device__ __constant__ float COS10[10] = {
    1.0f,  0.80901699437494745f,  0.30901699437494745f, -0.30901699437494745f, -0.80901699437494745f,
   -1.0f, -0.80901699437494745f, -0.30901699437494745f,  0.30901699437494745f,  0.80901699437494745f};
__device__ __constant__ float SIN10[10] = {
    0.0f,  0.58778525229247314f,  0.95105651629515357f,  0.95105651629515357f,  0.58778525229247314f,
    0.0f, -0.58778525229247314f, -0.95105651629515357f, -0.95105651629515357f, -0.58778525229247314f};

__global__ void precompute_h_kernel(const float* __restrict__ w) {
    // Let the dependent (main) kernel begin launching immediately; it will
    // griddepcontrol.wait before reading g_hvT.
    asm volatile("griddepcontrol.launch_dependents;");

    int d = blockIdx.x * blockDim.x + threadIdx.x;
    if (d >= DIM) return;
    const float4* wp = reinterpret_cast<const float4*>(w + d * 12);
    float4 w0 = wp[0], w1 = wp[1], w2 = wp[2];
    float a[6], b[6];
    a[0] = w0.x; b[0] = w0.y; a[1] = w0.z; b[1] = w0.w;
    a[2] = w1.x; b[2] = w1.y; a[3] = w1.z; b[3] = w1.w;
    a[4] = w2.x; b[4] = w2.y; a[5] = w2.z; b[5] = w2.w;

    float* hf = reinterpret_cast<float*>(g_hvT);
#pragma unroll
    for (int j = 0; j < NPTS; j++) {
        float acc = a[0] + ((j & 1) ? -a[5] : a[5]);
#pragma unroll
        for (int k = 1; k <= 4; k++) {
            int m = (k * j) % 10;
            acc += 2.0f * (a[k] * COS10[m] - b[k] * SIN10[m]);
        }
        // u64 slot (j, p=d/2); lo half for even d, hi half for odd d
        hf[(j * (DIM / 2) + (d >> 1)) * 2 + (d & 1)] = 0.1f * acc;
    }
}

// ---- packed f32x2 helpers ----
__device__ __forceinline__ unsigned long long pack2(float lo, float hi) {
    unsigned long long r;
    asm("mov.b64 %0, {%1, %2};" : "=l"(r) : "f"(lo), "f"(hi));
    return r;
}
__device__ __forceinline__ unsigned long long fma2(unsigned long long a,
                                                   unsigned long long b,
                                                   unsigned long long c) {
    unsigned long long d;
    asm("fma.rn.f32x2 %0, %1, %2, %3;" : "=l"(d) : "l"(a), "l"(b), "l"(c));
    return d;
}
__device__ __forceinline__ void unpack2(unsigned long long v, float& lo, float& hi) {
    asm("mov.b64 {%0, %1}, %2;" : "=f"(lo), "=f"(hi) : "l"(v));
}
__device__ __forceinline__ uint32_t smem_u32(const void* p) {
    return (uint32_t)__cvta_generic_to_shared(p);
}

__global__ void __launch_bounds__(THREADS)
global_filter_kernel(const float* __restrict__ x, float* __restrict__ y) {
    __shared__ __align__(16) char smem[SMEM_BYTES];

    int tid = threadIdx.x;
    int w   = tid >> 5;      // warp in block
    int t   = tid & 31;      // lane

    size_t f4base = (size_t)blockIdx.x * F4_PER_BLOCK + (size_t)w * F4_PER_WARP;
    const float4* xg = reinterpret_cast<const float4*>(x) + f4base;
    char* sw = smem + w * 2560;     // this warp's staging tile

    // Phase 1: coalesced global -> smem via cp.async (L1 bypass; x is streaming).
    // x is independent of the precompute kernel's output, so issue before the PDL wait.
#pragma unroll
    for (int k = 0; k < 5; k++) {
        uint32_t sa = smem_u32(sw + (t + 32 * k) * 16);
        const float4* ga = xg + t + 32 * k;
        asm volatile("cp.async.cg.shared.global [%0], [%1], 16;\n" :: "r"(sa), "l"(ga));
    }
    asm volatile("cp.async.commit_group;\n");

    // PDL: wait for precompute_h_kernel's stores to be visible before reading g_hvT.
    asm volatile("griddepcontrol.wait;");

    // Load packed filter pairs (coalesced, L2/L1 resident, 40KB total)
    int p = (blockIdx.x * 256 + w * 32 + t) & (DIM / 2 - 1);  // no intra-warp wrap
    unsigned long long hv[10];
#pragma unroll
    for (int j = 0; j < 10; j++) hv[j] = __ldg(&g_hvT[j * (DIM / 2) + p]);

    asm volatile("cp.async.wait_group 0;\n");
    __syncwarp();

    // Phase 2: each thread reads its OWN 80B (rows 2t, 2t+1 of this warp's tile).
    // LDS.128 at 80*t + 16*i: 16B aligned, conflict-free per 8-lane phase.
    const float4* sx = reinterpret_cast<const float4*>(sw + 80 * t);
    float4 r0 = sx[0], r1 = sx[1], r2 = sx[2], r3 = sx[3], r4 = sx[4];
    float xr[20] = {r0.x, r0.y, r0.z, r0.w, r1.x, r1.y, r1.z, r1.w, r2.x, r2.y,
                    r2.z, r2.w, r3.x, r3.y, r3.z, r3.w, r4.x, r4.y, r4.z, r4.w};

    unsigned long long xv[10];
#pragma unroll
    for (int j = 0; j < 10; j++) xv[j] = pack2(xr[j], xr[10 + j]);

    unsigned long long acc[10];
#pragma unroll
    for (int n = 0; n < 10; n++) acc[n] = 0ULL;
#pragma unroll
    for (int j = 0; j < 10; j++) {
#pragma unroll
        for (int n = 0; n < 10; n++) {
            acc[n] = fma2(hv[(n - j + 10) % 10], xv[j], acc[n]);
        }
    }

    // Phase 3: write y into OWN 80B region, then warp-coalesced streaming stores.
    float y0[10], y1[10];
#pragma unroll
    for (int n = 0; n < 10; n++) unpack2(acc[n], y0[n], y1[n]);

    float4* sy = reinterpret_cast<float4*>(sw + 80 * t);
    sy[0] = make_float4(y0[0], y0[1], y0[2], y0[3]);
    sy[1] = make_float4(y0[4], y0[5], y0[6], y0[7]);
    sy[2] = make_float4(y0[8], y0[9], y1[0], y1[1]);
    sy[3] = make_float4(y1[2], y1[3], y1[4], y1[5]);
    sy[4] = make_float4(y1[6], y1[7], y1[8], y1[9]);
    __syncwarp();

    float4* yg = reinterpret_cast<float4*>(y) + f4base;
    const float4* sr = reinterpret_cast<const float4*>(sw);
#pragma unroll
    for (int k = 0; k < 5; k++) {
        __stcs(yg + t + 32 * k, sr[t + 32 * k]);
    }
}

extern "C" void kernel_launch(void* const* d_in, const int* in_sizes, int n_in,
                              void* d_out, int out_size) {
    const float* x = (const float*)d_in[0];
    const float* w = (const float*)d_in[1];
    float* y = (float*)d_out;

    precompute_h_kernel<<<(DIM + 255) / 256, 256>>>(w);

    int nrows  = in_sizes[0] / NPTS;            // 8192*1024 = 8,388,608
    int blocks = nrows / ROWS_PER_BLOCK;        // 16384

    // Launch main kernel with programmatic stream serialization (PDL):
    // it may begin while precompute_h_kernel is still running.
    cudaLaunchConfig_t cfg = {};
    cfg.gridDim  = dim3((unsigned)blocks, 1, 1);
    cfg.blockDim = dim3(THREADS, 1, 1);
    cfg.dynamicSmemBytes = 0;
    cfg.stream = 0;
    cudaLaunchAttribute attr;
    attr.id = cudaLaunchAttributeProgrammaticStreamSerialization;
    attr.val.programmaticStreamSerializationAllowed = 1;
    cfg.attrs = &attr;
    cfg.numAttrs = 1;
    cudaLaunchKernelEx(&cfg, global_filter_kernel, x, y);
}